// round 3
// baseline (speedup 1.0000x reference)
#include <cuda_runtime.h>
#include <cstdint>

// ---------------- problem constants ----------------
#define BATCH 2
#define C3 256
#define HW 48           // lv3 spatial
#define M48 (HW*HW)     // 2304 patch positions
#define HP 50           // padded 48+2
#define NP 2500         // 50*50
#define NPS 2560        // padded GEMM dim (20 * 128)
#define KTILE 16
#define NKSTEPS 16      // 256 / 16
#define STAGES 3

// ---------------- scratch (device globals; no runtime alloc) ----------------
__device__ __align__(16) float g_lrp[BATCH * C3 * NPS];        // padded lr  [b][c][u]
__device__ __align__(16) float g_rfp[BATCH * C3 * NPS];        // padded refsr
__device__ __align__(16) float g_E[(size_t)BATCH * NPS * NPS]; // E[b][i][j]
__device__ __align__(16) float g_D[(size_t)BATCH * M48 * M48]; // D[b][m][l]
__device__ float g_SS[2 * BATCH * NP];
__device__ float g_invn[2 * BATCH * M48];
__device__ int   g_Hidx[BATCH * M48];
__device__ int   g_src[3 * BATCH * M48];

// ---------------- prep: zero-padded images ----------------
__global__ void prep_kernel(const float* __restrict__ lr, const float* __restrict__ refsr) {
    int t = blockIdx.x * blockDim.x + threadIdx.x;
    if (t >= 2 * BATCH * C3 * NPS) return;
    int u = t % NPS; int r = t / NPS;
    int c = r % C3; r /= C3;
    int b = r & 1; int which = r >> 1;
    float val = 0.f;
    if (u < NP) {
        int rr = u / HP, cc = u % HP;
        if (rr >= 1 && rr < 49 && cc >= 1 && cc < 49) {
            const float* src = which ? refsr : lr;
            val = src[((size_t)(b * C3 + c)) * M48 + (rr - 1) * HW + (cc - 1)];
        }
    }
    float* dst = which ? g_rfp : g_lrp;
    dst[((size_t)(b * C3 + c)) * NPS + u] = val;
}

// ---------------- per-pixel channel sum of squares ----------------
__global__ void ssq_kernel() {
    int t = blockIdx.x * blockDim.x + threadIdx.x;
    if (t >= 2 * BATCH * NP) return;
    int u = t % NP; int b = (t / NP) & 1; int which = t / (BATCH * NP);
    const float* src = (which ? g_rfp : g_lrp) + (size_t)b * C3 * NPS + u;
    float acc = 0.f;
#pragma unroll 8
    for (int c = 0; c < C3; c++) { float x = src[(size_t)c * NPS]; acc += x * x; }
    g_SS[t] = acc;
}

// ---------------- patch inverse norms ----------------
__global__ void norm_kernel() {
    int t = blockIdx.x * blockDim.x + threadIdx.x;
    if (t >= 2 * BATCH * M48) return;
    int m = t % M48; int b = (t / M48) & 1; int which = t / (BATCH * M48);
    int mi = m / HW, mj = m % HW;
    const float* S = g_SS + (which * BATCH + b) * NP;
    float s = 0.f;
#pragma unroll
    for (int di = 0; di < 3; di++)
#pragma unroll
        for (int dj = 0; dj < 3; dj++)
            s += S[(mi + di) * HP + mj + dj];
    g_invn[t] = 1.0f / fmaxf(sqrtf(s), 1e-12f);
}

// ---------------- SGEMM: E = lrp^T * rfp (2560x2560, K=256), cp.async pipeline ----------------
__global__ void __launch_bounds__(256) gemm_kernel() {
    int b = blockIdx.z;
    const float* A = g_lrp + (size_t)b * C3 * NPS;
    const float* B = g_rfp + (size_t)b * C3 * NPS;
    float* C = g_E + (size_t)b * NPS * NPS;

    __shared__ __align__(16) float As[STAGES][KTILE][128];
    __shared__ __align__(16) float Bs[STAGES][KTILE][128];

    int tid = threadIdx.x;
    int iBase = blockIdx.x * 128;
    int jBase = blockIdx.y * 128;
    int lk = tid >> 5;          // 0..7  (rows lk and lk+8)
    int lc = (tid & 31) << 2;   // 0..124
    const float* Aptr = A + (size_t)lk * NPS + iBase + lc;
    const float* Bptr = B + (size_t)lk * NPS + jBase + lc;

#define ISSUE(stage, kt) do {                                                          \
        uint32_t sa0 = (uint32_t)__cvta_generic_to_shared(&As[(stage)][lk][lc]);       \
        uint32_t sa1 = (uint32_t)__cvta_generic_to_shared(&As[(stage)][lk + 8][lc]);   \
        uint32_t sb0 = (uint32_t)__cvta_generic_to_shared(&Bs[(stage)][lk][lc]);       \
        uint32_t sb1 = (uint32_t)__cvta_generic_to_shared(&Bs[(stage)][lk + 8][lc]);   \
        const float* ga0 = Aptr + (size_t)(kt) * KTILE * NPS;                          \
        const float* ga1 = ga0 + (size_t)8 * NPS;                                      \
        const float* gb0 = Bptr + (size_t)(kt) * KTILE * NPS;                          \
        const float* gb1 = gb0 + (size_t)8 * NPS;                                      \
        asm volatile("cp.async.ca.shared.global [%0], [%1], 16;\n" :: "r"(sa0), "l"(ga0)); \
        asm volatile("cp.async.ca.shared.global [%0], [%1], 16;\n" :: "r"(sa1), "l"(ga1)); \
        asm volatile("cp.async.ca.shared.global [%0], [%1], 16;\n" :: "r"(sb0), "l"(gb0)); \
        asm volatile("cp.async.ca.shared.global [%0], [%1], 16;\n" :: "r"(sb1), "l"(gb1)); \
        asm volatile("cp.async.commit_group;\n" ::: "memory");                         \
    } while (0)

    ISSUE(0, 0);
    ISSUE(1, 1);

    int ty = tid >> 4, tx = tid & 15;   // 16x16 thread grid
    float acc[8][8];
#pragma unroll
    for (int i = 0; i < 8; i++)
#pragma unroll
        for (int j = 0; j < 8; j++) acc[i][j] = 0.f;

    for (int kt = 0; kt < NKSTEPS; kt++) {
        asm volatile("cp.async.wait_group 1;\n" ::: "memory");
        __syncthreads();
        if (kt + 2 < NKSTEPS) { int st = (kt + 2) % STAGES; ISSUE(st, kt + 2); }
        int cur = kt % STAGES;
#pragma unroll
        for (int kk = 0; kk < KTILE; kk++) {
            float ar[8], br[8];
            *(float4*)(ar)     = *(float4*)&As[cur][kk][ty * 4];
            *(float4*)(ar + 4) = *(float4*)&As[cur][kk][64 + ty * 4];
            *(float4*)(br)     = *(float4*)&Bs[cur][kk][tx * 4];
            *(float4*)(br + 4) = *(float4*)&Bs[cur][kk][64 + tx * 4];
#pragma unroll
            for (int i = 0; i < 8; i++)
#pragma unroll
                for (int j = 0; j < 8; j++) acc[i][j] += ar[i] * br[j];
        }
    }

#pragma unroll
    for (int half = 0; half < 2; half++) {
#pragma unroll
        for (int ii = 0; ii < 4; ii++) {
            int i = half * 4 + ii;
            int row = iBase + half * 64 + ty * 4 + ii;
            float* crow = C + (size_t)row * NPS + jBase;
            *(float4*)(crow + tx * 4)      = make_float4(acc[i][0], acc[i][1], acc[i][2], acc[i][3]);
            *(float4*)(crow + 64 + tx * 4) = make_float4(acc[i][4], acc[i][5], acc[i][6], acc[i][7]);
        }
    }
#undef ISSUE
}

// ---------------- aggregate 9 E-taps -> D row, plus argmax over keys ----------------
__global__ void __launch_bounds__(256) agg_kernel() {
    int m = blockIdx.x, b = blockIdx.y;
    int mi = m / HW, mj = m % HW;
    const float* Eb = g_E + (size_t)b * NPS * NPS;
    float inq = g_invn[(0 * BATCH + b) * M48 + m];
    const float* invk = g_invn + (1 * BATCH + b) * M48;
    float* Drow = g_D + ((size_t)b * M48 + m) * M48;

    const float* base0 = Eb + (size_t)((mi + 0) * HP + mj) * NPS + 0 * HP;
    const float* base1 = Eb + (size_t)((mi + 1) * HP + mj) * NPS + 1 * HP;
    const float* base2 = Eb + (size_t)((mi + 2) * HP + mj) * NPS + 2 * HP;

    float bv = -1e30f; int bi = 1 << 30;
    for (int l = threadIdx.x; l < M48; l += 256) {
        int li = l / HW, lj = l % HW;
        int o = li * HP + lj;
        float s = base0[o] + base0[o + NPS + 1] + base0[o + 2 * NPS + 2]
                + base1[o] + base1[o + NPS + 1] + base1[o + 2 * NPS + 2]
                + base2[o] + base2[o + NPS + 1] + base2[o + 2 * NPS + 2];
        float val = s * inq * invk[l];
        Drow[l] = val;
        if (val > bv) { bv = val; bi = l; }
    }
    __shared__ float rv[256];
    __shared__ int   ri[256];
    rv[threadIdx.x] = bv; ri[threadIdx.x] = bi;
    __syncthreads();
    for (int s = 128; s > 0; s >>= 1) {
        if (threadIdx.x < s) {
            float v2 = rv[threadIdx.x + s]; int i2 = ri[threadIdx.x + s];
            if (v2 > rv[threadIdx.x] || (v2 == rv[threadIdx.x] && i2 < ri[threadIdx.x])) {
                rv[threadIdx.x] = v2; ri[threadIdx.x] = i2;
            }
        }
        __syncthreads();
    }
    if (threadIdx.x == 0) g_Hidx[b * M48 + m] = ri[0];
}

// ---------------- stable top-3 of D[m][Hidx[l]] over l; writes soft + src ----------------
__global__ void __launch_bounds__(256) topk_kernel(float* __restrict__ outS) {
    int m = blockIdx.x, b = blockIdx.y;
    __shared__ float rowv[M48];
    __shared__ int   hs[M48];
    __shared__ float rv[256];
    __shared__ int   ri[256];
    const float* Drow = g_D + ((size_t)b * M48 + m) * M48;
    for (int j = threadIdx.x; j < M48; j += 256) {
        rowv[j] = Drow[j];
        hs[j] = g_Hidx[b * M48 + j];
    }
    __syncthreads();
    int ch0 = -1, ch1 = -1, ch2 = -1;
    for (int pass = 0; pass < 3; pass++) {
        float bv = -1e30f; int bi = 1 << 30;
        for (int j = threadIdx.x; j < M48; j += 256) {
            if (j == ch0 || j == ch1 || j == ch2) continue;
            float v = rowv[hs[j]];
            if (v > bv || (v == bv && j < bi)) { bv = v; bi = j; }
        }
        rv[threadIdx.x] = bv; ri[threadIdx.x] = bi;
        __syncthreads();
        for (int s = 128; s > 0; s >>= 1) {
            if (threadIdx.x < s) {
                float v2 = rv[threadIdx.x + s]; int i2 = ri[threadIdx.x + s];
                if (v2 > rv[threadIdx.x] || (v2 == rv[threadIdx.x] && i2 < ri[threadIdx.x])) {
                    rv[threadIdx.x] = v2; ri[threadIdx.x] = i2;
                }
            }
            __syncthreads();
        }
        int sel = ri[0]; float selv = rv[0];
        if (pass == 0) ch0 = sel; else if (pass == 1) ch1 = sel; else ch2 = sel;
        if (threadIdx.x == 0) {
            outS[(pass * BATCH + b) * M48 + m] = selv;
            g_src[(pass * BATCH + b) * M48 + m] = hs[sel];
        }
        __syncthreads();
    }
}

// ---------------- transfer: fold(gather(unfold(ref))) / 9, any pyramid level ----------------
__global__ void transfer_kernel(const float* __restrict__ ref, float* __restrict__ out,
                                int R, int C, int S, int CCH) {
    int t = blockIdx.x * blockDim.x + threadIdx.x;
    int nCh = C / CCH;
    int total = 3 * BATCH * nCh * S * S;
    if (t >= total) return;
    int x = t % S; int tmp = t / S;
    int y = tmp % S; tmp /= S;
    int cc = tmp % nCh; tmp /= nCh;
    int b = tmp & 1; int i = tmp >> 1;

    const int* srcTab = g_src + (i * BATCH + b) * M48;
    int yp = y + R, xp = x + R;
    int v = yp - 3 * R + 1; int milo = (v <= 0) ? 0 : (v + R - 1) / R;
    int mihi = yp / R; if (mihi > 47) mihi = 47;
    v = xp - 3 * R + 1; int mjlo = (v <= 0) ? 0 : (v + R - 1) / R;
    int mjhi = xp / R; if (mjhi > 47) mjhi = 47;

    float mk[9]; int off[9];
#pragma unroll
    for (int a = 0; a < 3; a++) {
        int mi = milo + a;
#pragma unroll
        for (int e = 0; e < 3; e++) {
            int mj = mjlo + e;
            int u = a * 3 + e;
            mk[u] = 0.f; off[u] = 0;
            if (mi <= mihi && mj <= mjhi) {
                int s = srcTab[mi * HW + mj];
                int smi = s / HW, smj = s % HW;
                int ry = y + (smi - mi) * R;
                int rx = x + (smj - mj) * R;
                if (ry >= 0 && ry < S && rx >= 0 && rx < S) { off[u] = ry * S + rx; mk[u] = 1.0f; }
            }
        }
    }
    int c0 = cc * CCH;
    const float* refb = ref + ((size_t)(b * C + c0)) * S * S;
    float* outb = out + ((size_t)((i * BATCH + b) * C + c0)) * S * S + y * S + x;
    for (int c = 0; c < CCH; c++) {
        const float* rc = refb + (size_t)c * S * S;
        float acc = 0.f;
#pragma unroll
        for (int u = 0; u < 9; u++) acc += mk[u] * __ldg(rc + off[u]);
        outb[(size_t)c * S * S] = acc * (1.0f / 9.0f);
    }
}

// ---------------- launch ----------------
extern "C" void kernel_launch(void* const* d_in, const int* in_sizes, int n_in,
                              void* d_out, int out_size) {
    const float* lr    = (const float*)d_in[0];
    const float* refsr = (const float*)d_in[1];
    const float* ref1  = (const float*)d_in[2];  // (2,64,192,192)
    const float* ref2  = (const float*)d_in[3];  // (2,128,96,96)
    const float* ref3  = (const float*)d_in[4];  // (2,256,48,48)
    float* out = (float*)d_out;

    float* outS  = out;
    float* outT3 = outS + 3 * BATCH * M48;
    float* outT2 = outT3 + 3 * BATCH * C3 * M48;
    float* outT1 = outT2 + 3 * BATCH * 128 * 96 * 96;

    {
        int n = 2 * BATCH * C3 * NPS;
        prep_kernel<<<(n + 255) / 256, 256>>>(lr, refsr);
    }
    ssq_kernel<<<(2 * BATCH * NP + 255) / 256, 256>>>();
    norm_kernel<<<(2 * BATCH * M48 + 255) / 256, 256>>>();
    gemm_kernel<<<dim3(20, 20, BATCH), 256>>>();
    agg_kernel<<<dim3(M48, BATCH), 256>>>();
    topk_kernel<<<dim3(M48, BATCH), 256>>>(outS);

    {   // lv3: R=1, C=256, S=48, CCH=8
        int n = 3 * BATCH * (C3 / 8) * 48 * 48;
        transfer_kernel<<<(n + 255) / 256, 256>>>(ref3, outT3, 1, 256, 48, 8);
    }
    {   // lv2: R=2, C=128, S=96, CCH=8
        int n = 3 * BATCH * (128 / 8) * 96 * 96;
        transfer_kernel<<<(n + 255) / 256, 256>>>(ref2, outT2, 2, 128, 96, 8);
    }
    {   // lv1: R=4, C=64, S=192, CCH=8
        int n = 3 * BATCH * (64 / 8) * 192 * 192;
        transfer_kernel<<<(n + 255) / 256, 256>>>(ref1, outT1, 4, 64, 192, 8);
    }
}

// round 4
// speedup vs baseline: 1.1082x; 1.1082x over previous
#include <cuda_runtime.h>
#include <cstdint>

// ---------------- problem constants ----------------
#define BATCH 2
#define C3 256
#define HW 48           // lv3 spatial
#define M48 (HW*HW)     // 2304 patch positions
#define HP 50           // padded 48+2
#define NP 2500         // 50*50
#define NPS 2560        // padded GEMM dim (20 * 128)
#define KTILE 16
#define NKSTEPS 16      // 256 / 16
#define STAGES 3

// ---------------- scratch (device globals; no runtime alloc) ----------------
__device__ __align__(16) float g_lrp[BATCH * C3 * NPS];        // padded lr  [b][c][u]
__device__ __align__(16) float g_rfp[BATCH * C3 * NPS];        // padded refsr
__device__ __align__(16) float g_E[(size_t)BATCH * NPS * NPS]; // E[b][i][j]
__device__ __align__(16) float g_D[(size_t)BATCH * M48 * M48]; // D[b][m][l]
__device__ float g_SS[2 * BATCH * NP];
__device__ float g_invn[2 * BATCH * M48];
__device__ int   g_Hidx[BATCH * M48];
__device__ int   g_src[3 * BATCH * M48];

// ---------------- prep: zero-padded images ----------------
__global__ void prep_kernel(const float* __restrict__ lr, const float* __restrict__ refsr) {
    int t = blockIdx.x * blockDim.x + threadIdx.x;
    if (t >= 2 * BATCH * C3 * NPS) return;
    int u = t % NPS; int r = t / NPS;
    int c = r % C3; r /= C3;
    int b = r & 1; int which = r >> 1;
    float val = 0.f;
    if (u < NP) {
        int rr = u / HP, cc = u % HP;
        if (rr >= 1 && rr < 49 && cc >= 1 && cc < 49) {
            const float* src = which ? refsr : lr;
            val = src[((size_t)(b * C3 + c)) * M48 + (rr - 1) * HW + (cc - 1)];
        }
    }
    float* dst = which ? g_rfp : g_lrp;
    dst[((size_t)(b * C3 + c)) * NPS + u] = val;
}

// ---------------- per-pixel channel sum of squares ----------------
__global__ void ssq_kernel() {
    int t = blockIdx.x * blockDim.x + threadIdx.x;
    if (t >= 2 * BATCH * NP) return;
    int u = t % NP; int b = (t / NP) & 1; int which = t / (BATCH * NP);
    const float* src = (which ? g_rfp : g_lrp) + (size_t)b * C3 * NPS + u;
    float acc = 0.f;
#pragma unroll 8
    for (int c = 0; c < C3; c++) { float x = src[(size_t)c * NPS]; acc += x * x; }
    g_SS[t] = acc;
}

// ---------------- patch inverse norms ----------------
__global__ void norm_kernel() {
    int t = blockIdx.x * blockDim.x + threadIdx.x;
    if (t >= 2 * BATCH * M48) return;
    int m = t % M48; int b = (t / M48) & 1; int which = t / (BATCH * M48);
    int mi = m / HW, mj = m % HW;
    const float* S = g_SS + (which * BATCH + b) * NP;
    float s = 0.f;
#pragma unroll
    for (int di = 0; di < 3; di++)
#pragma unroll
        for (int dj = 0; dj < 3; dj++)
            s += S[(mi + di) * HP + mj + dj];
    g_invn[t] = 1.0f / fmaxf(sqrtf(s), 1e-12f);
}

// ---------------- SGEMM: E = lrp^T * rfp (2560x2560, K=256), FFMA2 + cp.async ----------------
__global__ void __launch_bounds__(256) gemm_kernel() {
    int b = blockIdx.z;
    const float* A = g_lrp + (size_t)b * C3 * NPS;
    const float* B = g_rfp + (size_t)b * C3 * NPS;
    float* C = g_E + (size_t)b * NPS * NPS;

    __shared__ __align__(16) float As[STAGES][KTILE][128];
    __shared__ __align__(16) float Bs[STAGES][KTILE][128];

    int tid = threadIdx.x;
    int iBase = blockIdx.x * 128;
    int jBase = blockIdx.y * 128;
    int lk = tid >> 5;          // 0..7  (rows lk and lk+8)
    int lc = (tid & 31) << 2;   // 0..124
    const float* Aptr = A + (size_t)lk * NPS + iBase + lc;
    const float* Bptr = B + (size_t)lk * NPS + jBase + lc;

#define ISSUE(stage, kt) do {                                                          \
        uint32_t sa0 = (uint32_t)__cvta_generic_to_shared(&As[(stage)][lk][lc]);       \
        uint32_t sa1 = (uint32_t)__cvta_generic_to_shared(&As[(stage)][lk + 8][lc]);   \
        uint32_t sb0 = (uint32_t)__cvta_generic_to_shared(&Bs[(stage)][lk][lc]);       \
        uint32_t sb1 = (uint32_t)__cvta_generic_to_shared(&Bs[(stage)][lk + 8][lc]);   \
        const float* ga0 = Aptr + (size_t)(kt) * KTILE * NPS;                          \
        const float* ga1 = ga0 + (size_t)8 * NPS;                                      \
        const float* gb0 = Bptr + (size_t)(kt) * KTILE * NPS;                          \
        const float* gb1 = gb0 + (size_t)8 * NPS;                                      \
        asm volatile("cp.async.ca.shared.global [%0], [%1], 16;\n" :: "r"(sa0), "l"(ga0)); \
        asm volatile("cp.async.ca.shared.global [%0], [%1], 16;\n" :: "r"(sa1), "l"(ga1)); \
        asm volatile("cp.async.ca.shared.global [%0], [%1], 16;\n" :: "r"(sb0), "l"(gb0)); \
        asm volatile("cp.async.ca.shared.global [%0], [%1], 16;\n" :: "r"(sb1), "l"(gb1)); \
        asm volatile("cp.async.commit_group;\n" ::: "memory");                         \
    } while (0)

    ISSUE(0, 0);
    ISSUE(1, 1);

    int ty = tid >> 4, tx = tid & 15;   // 16x16 thread grid

    // packed f32x2 accumulators: accp[i][jp] holds columns (2*jp, 2*jp+1) of 8-wide j frag
    unsigned long long accp[8][4];
#pragma unroll
    for (int i = 0; i < 8; i++)
#pragma unroll
        for (int j = 0; j < 4; j++) accp[i][j] = 0ull;

    for (int kt = 0; kt < NKSTEPS; kt++) {
        asm volatile("cp.async.wait_group 1;\n" ::: "memory");
        __syncthreads();
        if (kt + 2 < NKSTEPS) { int st = (kt + 2) % STAGES; ISSUE(st, kt + 2); }
        int cur = kt % STAGES;
#pragma unroll
        for (int kk = 0; kk < KTILE; kk++) {
            float4 a0 = *(float4*)&As[cur][kk][ty * 4];
            float4 a1 = *(float4*)&As[cur][kk][64 + ty * 4];
            // B fragments loaded as packed pairs (bit-identical reinterpret)
            unsigned long long bp[4];
            *(ulonglong2*)(bp)     = *(ulonglong2*)&Bs[cur][kk][tx * 4];
            *(ulonglong2*)(bp + 2) = *(ulonglong2*)&Bs[cur][kk][64 + tx * 4];
            float ar[8] = {a0.x, a0.y, a0.z, a0.w, a1.x, a1.y, a1.z, a1.w};
#pragma unroll
            for (int i = 0; i < 8; i++) {
                unsigned long long a2;
                asm("mov.b64 %0, {%1, %1};" : "=l"(a2) : "r"(__float_as_uint(ar[i])));
#pragma unroll
                for (int jp = 0; jp < 4; jp++) {
                    asm("fma.rn.f32x2 %0, %1, %2, %0;"
                        : "+l"(accp[i][jp]) : "l"(a2), "l"(bp[jp]));
                }
            }
        }
    }

#pragma unroll
    for (int half = 0; half < 2; half++) {
#pragma unroll
        for (int ii = 0; ii < 4; ii++) {
            int i = half * 4 + ii;
            int row = iBase + half * 64 + ty * 4 + ii;
            float* crow = C + (size_t)row * NPS + jBase;
            *(ulonglong2*)(crow + tx * 4)      = make_ulonglong2(accp[i][0], accp[i][1]);
            *(ulonglong2*)(crow + 64 + tx * 4) = make_ulonglong2(accp[i][2], accp[i][3]);
        }
    }
#undef ISSUE
}

// ---------------- aggregate 9 E-taps -> D row, plus argmax over keys ----------------
__global__ void __launch_bounds__(256) agg_kernel() {
    int m = blockIdx.x, b = blockIdx.y;
    int mi = m / HW, mj = m % HW;
    const float* Eb = g_E + (size_t)b * NPS * NPS;
    float inq = g_invn[(0 * BATCH + b) * M48 + m];
    const float* invk = g_invn + (1 * BATCH + b) * M48;
    float* Drow = g_D + ((size_t)b * M48 + m) * M48;

    const float* base0 = Eb + (size_t)((mi + 0) * HP + mj) * NPS + 0 * HP;
    const float* base1 = Eb + (size_t)((mi + 1) * HP + mj) * NPS + 1 * HP;
    const float* base2 = Eb + (size_t)((mi + 2) * HP + mj) * NPS + 2 * HP;

    float bv = -1e30f; int bi = 1 << 30;
    for (int l = threadIdx.x; l < M48; l += 256) {
        int li = l / HW, lj = l % HW;
        int o = li * HP + lj;
        float s = base0[o] + base0[o + NPS + 1] + base0[o + 2 * NPS + 2]
                + base1[o] + base1[o + NPS + 1] + base1[o + 2 * NPS + 2]
                + base2[o] + base2[o + NPS + 1] + base2[o + 2 * NPS + 2];
        float val = s * inq * invk[l];
        Drow[l] = val;
        if (val > bv) { bv = val; bi = l; }
    }
    __shared__ float rv[256];
    __shared__ int   ri[256];
    rv[threadIdx.x] = bv; ri[threadIdx.x] = bi;
    __syncthreads();
    for (int s = 128; s > 0; s >>= 1) {
        if (threadIdx.x < s) {
            float v2 = rv[threadIdx.x + s]; int i2 = ri[threadIdx.x + s];
            if (v2 > rv[threadIdx.x] || (v2 == rv[threadIdx.x] && i2 < ri[threadIdx.x])) {
                rv[threadIdx.x] = v2; ri[threadIdx.x] = i2;
            }
        }
        __syncthreads();
    }
    if (threadIdx.x == 0) g_Hidx[b * M48 + m] = ri[0];
}

// ---------------- stable top-3 of D[m][Hidx[l]] over l; writes soft + src ----------------
__global__ void __launch_bounds__(256) topk_kernel(float* __restrict__ outS) {
    int m = blockIdx.x, b = blockIdx.y;
    __shared__ float rowv[M48];
    __shared__ int   hs[M48];
    __shared__ float rv[256];
    __shared__ int   ri[256];
    const float* Drow = g_D + ((size_t)b * M48 + m) * M48;
    for (int j = threadIdx.x; j < M48; j += 256) {
        rowv[j] = Drow[j];
        hs[j] = g_Hidx[b * M48 + j];
    }
    __syncthreads();
    int ch0 = -1, ch1 = -1, ch2 = -1;
    for (int pass = 0; pass < 3; pass++) {
        float bv = -1e30f; int bi = 1 << 30;
        for (int j = threadIdx.x; j < M48; j += 256) {
            if (j == ch0 || j == ch1 || j == ch2) continue;
            float v = rowv[hs[j]];
            if (v > bv || (v == bv && j < bi)) { bv = v; bi = j; }
        }
        rv[threadIdx.x] = bv; ri[threadIdx.x] = bi;
        __syncthreads();
        for (int s = 128; s > 0; s >>= 1) {
            if (threadIdx.x < s) {
                float v2 = rv[threadIdx.x + s]; int i2 = ri[threadIdx.x + s];
                if (v2 > rv[threadIdx.x] || (v2 == rv[threadIdx.x] && i2 < ri[threadIdx.x])) {
                    rv[threadIdx.x] = v2; ri[threadIdx.x] = i2;
                }
            }
            __syncthreads();
        }
        int sel = ri[0]; float selv = rv[0];
        if (pass == 0) ch0 = sel; else if (pass == 1) ch1 = sel; else ch2 = sel;
        if (threadIdx.x == 0) {
            outS[(pass * BATCH + b) * M48 + m] = selv;
            g_src[(pass * BATCH + b) * M48 + m] = hs[sel];
        }
        __syncthreads();
    }
}

// ---------------- transfer: fold(gather(unfold(ref))) / 9, any pyramid level ----------------
__global__ void transfer_kernel(const float* __restrict__ ref, float* __restrict__ out,
                                int R, int C, int S, int CCH) {
    int t = blockIdx.x * blockDim.x + threadIdx.x;
    int nCh = C / CCH;
    int total = 3 * BATCH * nCh * S * S;
    if (t >= total) return;
    int x = t % S; int tmp = t / S;
    int y = tmp % S; tmp /= S;
    int cc = tmp % nCh; tmp /= nCh;
    int b = tmp & 1; int i = tmp >> 1;

    const int* srcTab = g_src + (i * BATCH + b) * M48;
    int yp = y + R, xp = x + R;
    int v = yp - 3 * R + 1; int milo = (v <= 0) ? 0 : (v + R - 1) / R;
    int mihi = yp / R; if (mihi > 47) mihi = 47;
    v = xp - 3 * R + 1; int mjlo = (v <= 0) ? 0 : (v + R - 1) / R;
    int mjhi = xp / R; if (mjhi > 47) mjhi = 47;

    float mk[9]; int off[9];
#pragma unroll
    for (int a = 0; a < 3; a++) {
        int mi = milo + a;
#pragma unroll
        for (int e = 0; e < 3; e++) {
            int mj = mjlo + e;
            int u = a * 3 + e;
            mk[u] = 0.f; off[u] = 0;
            if (mi <= mihi && mj <= mjhi) {
                int s = srcTab[mi * HW + mj];
                int smi = s / HW, smj = s % HW;
                int ry = y + (smi - mi) * R;
                int rx = x + (smj - mj) * R;
                if (ry >= 0 && ry < S && rx >= 0 && rx < S) { off[u] = ry * S + rx; mk[u] = 1.0f; }
            }
        }
    }
    int c0 = cc * CCH;
    const float* refb = ref + ((size_t)(b * C + c0)) * S * S;
    float* outb = out + ((size_t)((i * BATCH + b) * C + c0)) * S * S + y * S + x;
    for (int c = 0; c < CCH; c++) {
        const float* rc = refb + (size_t)c * S * S;
        float acc = 0.f;
#pragma unroll
        for (int u = 0; u < 9; u++) acc += mk[u] * __ldg(rc + off[u]);
        outb[(size_t)c * S * S] = acc * (1.0f / 9.0f);
    }
}

// ---------------- launch ----------------
extern "C" void kernel_launch(void* const* d_in, const int* in_sizes, int n_in,
                              void* d_out, int out_size) {
    const float* lr    = (const float*)d_in[0];
    const float* refsr = (const float*)d_in[1];
    const float* ref1  = (const float*)d_in[2];  // (2,64,192,192)
    const float* ref2  = (const float*)d_in[3];  // (2,128,96,96)
    const float* ref3  = (const float*)d_in[4];  // (2,256,48,48)
    float* out = (float*)d_out;

    float* outS  = out;
    float* outT3 = outS + 3 * BATCH * M48;
    float* outT2 = outT3 + 3 * BATCH * C3 * M48;
    float* outT1 = outT2 + 3 * BATCH * 128 * 96 * 96;

    {
        int n = 2 * BATCH * C3 * NPS;
        prep_kernel<<<(n + 255) / 256, 256>>>(lr, refsr);
    }
    ssq_kernel<<<(2 * BATCH * NP + 255) / 256, 256>>>();
    norm_kernel<<<(2 * BATCH * M48 + 255) / 256, 256>>>();
    gemm_kernel<<<dim3(20, 20, BATCH), 256>>>();
    agg_kernel<<<dim3(M48, BATCH), 256>>>();
    topk_kernel<<<dim3(M48, BATCH), 256>>>(outS);

    {   // lv3: R=1, C=256, S=48, CCH=32
        int n = 3 * BATCH * (C3 / 32) * 48 * 48;
        transfer_kernel<<<(n + 255) / 256, 256>>>(ref3, outT3, 1, 256, 48, 32);
    }
    {   // lv2: R=2, C=128, S=96, CCH=32
        int n = 3 * BATCH * (128 / 32) * 96 * 96;
        transfer_kernel<<<(n + 255) / 256, 256>>>(ref2, outT2, 2, 128, 96, 32);
    }
    {   // lv1: R=4, C=64, S=192, CCH=32
        int n = 3 * BATCH * (64 / 32) * 192 * 192;
        transfer_kernel<<<(n + 255) / 256, 256>>>(ref1, outT1, 4, 64, 192, 32);
    }
}